// round 17
// baseline (speedup 1.0000x reference)
#include <cuda_runtime.h>
#include <cstdint>

// EPG simulation, 16 threads per batch: threads 0-9 hold 2 EPG states,
// thread 10 holds state 20 + a contained junk slot, threads 11-15 are zero
// sinks. 8192 warps chip-wide (2x R16) for latency hiding. Block-wide TMA
// bulk store (one fence+store per block-pulse), triple-buffered ring,
// chunked coefficient precompute.

constexpr int NS   = 21;
constexpr int ROW  = NS * 5;            // 105 floats per (pulse,batch)
constexpr int NP   = 64;
constexpr int THREADS = 128;            // 4 warps
constexpr int BPW  = 2;                 // batches per warp (16 threads each)
constexpr int BPB  = 8;                 // batches per block
constexpr int BST  = BPB * ROW;         // 840 floats = 3360 B block stage
constexpr int NBUF = 3;                 // TMA ring depth
constexpr int CHUNK = 8;                // pulses per coefficient chunk
constexpr int CROW  = CHUNK * 12 + 4;   // 100 floats per batch

__global__ __launch_bounds__(THREADS)
void epg_kernel(const float* __restrict__ fa,
                const float* __restrict__ ph,
                const float* __restrict__ T1,
                const float* __restrict__ T2,
                const float* __restrict__ B0,
                const float* __restrict__ B1,
                const int*   __restrict__ trp,
                float* __restrict__ out,
                int n_pulses, int n_batch)
{
    __shared__ __align__(16) float4 pc4[NP];            // {fa, cos p, sin p, cos 2p}
    __shared__ float                ps2[NP];            // sin 2p
    __shared__ __align__(16) float  sbv[BPB][4];        // er, ei, E1, b1h
    __shared__ __align__(16) float  coef[BPB][CROW];    // 3200 B per chunk
    __shared__ __align__(16) float  stage[NBUF][BST];   // 10080 B ring

    const int tid  = threadIdx.x;
    const int warp = tid >> 5;
    const int lane = tid & 31;
    const int g    = lane >> 4;          // batch within warp (0..1)
    const int t    = lane & 15;          // fragment within batch (0..15)
    const int bwl  = warp * BPW + g;     // batch within block (0..7)

    const int tri = *trp;
    const float TR = (tri > 0 && tri < 1000000) ? (float)tri : __int_as_float(tri);

    // Pulse constants
    for (int p = tid; p < n_pulses; p += THREADS) {
        float s, c;
        sincosf(ph[p], &s, &c);
        pc4[p] = make_float4(fa[p], c, s, c * c - s * s);
        ps2[p] = 2.f * c * s;
    }
    // Per-batch constants
    if (tid < BPB) {
        int b2 = blockIdx.x * BPB + tid;
        if (b2 >= n_batch) b2 = n_batch - 1;
        const float E1 = __expf(-TR / T1[b2]);
        const float E2 = __expf(-TR / T2[b2]);
        float b0r, b0i;
        sincosf(6.283185307179586e-3f * B0[b2] * TR, &b0i, &b0r);
        sbv[tid][0] = E2 * b0r;
        sbv[tid][1] = E2 * b0i;
        sbv[tid][2] = E1;
        sbv[tid][3] = B1[b2] * 0.5f;
    }
    __syncthreads();

    const bool t0   = (t == 0);
    const bool seal = (t == 10);          // slot0 = state 20: Fm must be 0
    const float rec = t0 ? (1.f - sbv[bwl][2]) : 0.f;

    // Two state slots: global states 2t, 2t+1 (t<=9); t==10: state 20 + junk 21
    float fp0r=0.f, fp0i=0.f, fm0r=0.f, fm0i=0.f, z0=0.f;
    float fp1r=0.f, fp1i=0.f, fm1r=0.f, fm1i=0.f, z1=0.f;
    if (t0) z0 = 1.f;

    const size_t pstride = (size_t)n_batch * ROW;
    float* const oblk = out + (size_t)blockIdx.x * BST;
    float* const rowb = &stage[0][bwl * ROW + t * 10];  // buffer-0 row base
    const uint32_t smb = (uint32_t)__cvta_generic_to_shared(&stage[0][0]);
    const float* const mycf = &coef[bwl][0];
    const bool leader = (tid == 0);

    int buf = 0;
    const int chunks = (n_pulses + CHUNK - 1) / CHUNK;
    for (int c = 0; c < chunks; ++c) {
        __syncthreads();                 // prior chunk's coef reads complete

        // ---- precompute 64 coefficient sets (tid < 64) ----
        if (tid < BPB * CHUNK) {
            const int bl = tid >> 3;     // batch (0..7)
            const int pp = tid & 7;      // pulse within chunk
            const int p  = c * CHUNK + pp;
            if (p < n_pulses) {
                const float4 pc = pc4[p];
                const float  s2 = ps2[p];
                const float  cp = pc.y, sp = pc.z, c2 = pc.w;
                const float er = sbv[bl][0], ei = sbv[bl][1];
                const float E1 = sbv[bl][2], b1h = sbv[bl][3];
                float sa, ca;
                __sincosf(pc.x * b1h, &sa, &ca);
                const float ca2 = ca*ca, sa2 = sa*sa, casa = ca*sa;
                const float w2r = er*c2 - ei*s2, w2i = er*s2 + ei*c2;
                const float w1r = er*cp - ei*sp, w1i = er*sp + ei*cp;
                const float q1  = casa*E1;
                float4* dst = (float4*)&coef[bl][pp * 12];
                dst[0] = make_float4(ca2*er, ca2*ei, sa2*w2r, sa2*w2i);   // A, B
                dst[1] = make_float4(-casa*w1i, casa*w1r, q1*cp, q1*sp);  // C, zc, zs
                dst[2] = make_float4((ca2 - sa2)*E1, 0.f, 0.f, 0.f);      // q2
            }
        }
        __syncthreads();

        const int pend = (n_pulses - c * CHUNK < CHUNK) ? (n_pulses - c * CHUNK) : CHUNK;
        for (int pp = 0; pp < pend; ++pp) {
            const int p = c * CHUNK + pp;
            const float4 c0 = *(const float4*)(mycf + pp * 12);
            const float4 c1 = *(const float4*)(mycf + pp * 12 + 4);
            const float  q2 = mycf[pp * 12 + 8];
            const float ar = c0.x, ai = c0.y, br = c0.z, bi = c0.w;
            const float cr = c1.x, ci = c1.y, zc = c1.z, zs = c1.w;

            // Boundary values from OLD state (shuffles issue early):
            //  T,Z of slot1 -> next thread's slot 0
            const float ocFr = ar*fp1r - ai*fp1i + br*fm1r + bi*fm1i + cr*z1;
            const float ocFi = ar*fp1i + ai*fp1r - br*fm1i + bi*fm1r + ci*z1;
            const float ocZ  = q2*z1 + zc*(fp1i - fm1i) - zs*(fp1r + fm1r);
            //  M of slot0 -> previous thread's slot 1 Fm
            const float oMr  = ar*fm0r + ai*fm0i + br*fp0r - bi*fp0i + cr*z0;
            const float oMi  = ar*fm0i - ai*fm0r - br*fp0i - bi*fp0r - ci*z0;

            float icFr = __shfl_up_sync(0xffffffffu, ocFr, 1);
            float icFi = __shfl_up_sync(0xffffffffu, ocFi, 1);
            float icZ  = __shfl_up_sync(0xffffffffu, ocZ,  1);
            float iMr  = __shfl_down_sync(0xffffffffu, oMr, 1);
            float iMi  = __shfl_down_sync(0xffffffffu, oMi, 1);
            // t0: state-0 zero; t>=11 sinks stay zero (also guards batch edges)
            if (t0 | (t >= 11)) { icFr = 0.f; icFi = 0.f; icZ = 0.f; }
            // t10: junk-21 Fm = 0 (natural from t11's zero mix); t15: cross-batch guard
            if (t >= 10) { iMr = 0.f; iMi = 0.f; }

            // Remaining new values from OLD state (overlaps shuffle latency)
            const float nfp1r = ar*fp0r - ai*fp0i + br*fm0r + bi*fm0i + cr*z0;
            const float nfp1i = ar*fp0i + ai*fp0r - br*fm0i + bi*fm0r + ci*z0;
            const float nz1   = q2*z0 + zc*(fp0i - fm0i) - zs*(fp0r + fm0r) + rec;
            const float nfm0r = ar*fm1r + ai*fm1i + br*fp1r - bi*fp1i + cr*z1;
            const float nfm0i = ar*fm1i - ai*fm1r - br*fp1i - bi*fp1r - ci*z1;

            // Commit (all olds consumed above)
            fp0r = icFr; fp0i = icFi; z0 = icZ;
            fp1r = nfp1r; fp1i = nfp1i; z1 = nz1;
            fm0r = seal ? 0.f : nfm0r;    // state 20 Fm = 0 (junk-21 mix discarded)
            fm0i = seal ? 0.f : nfm0i;
            fm1r = iMr; fm1i = iMi;

            // --- ring recycle: store issued 3 pulses ago (same buffer) done reading ---
            if (leader)
                asm volatile("cp.async.bulk.wait_group.read 2;" ::: "memory");
            __syncthreads();

            // Stage: t<=9: 10 floats, t==10: 5 floats. Word addr 9g+10t+i mod 32
            // distinct across the 22 active lanes -> conflict-free STS.
            if (t <= 10) {
                float* row = rowb + buf * BST;
                row[0] = fp0r; row[1] = fp0i; row[2] = fm0r; row[3] = fm0i; row[4] = z0;
                if (t <= 9) {
                    row[5] = fp1r; row[6] = fp1i; row[7] = fm1r; row[8] = fm1i; row[9] = z1;
                }
            }
            __syncthreads();

            // ONE block-wide TMA bulk store: 3360B shared -> global
            if (leader) {
                asm volatile("fence.proxy.async.shared::cta;" ::: "memory");
                asm volatile("cp.async.bulk.global.shared::cta.bulk_group [%0], [%1], %2;"
                             :: "l"(oblk + (size_t)p * pstride),
                                "r"(smb + (uint32_t)(buf * BST * 4)),
                                "r"(BST * 4) : "memory");
                asm volatile("cp.async.bulk.commit_group;" ::: "memory");
            }
            buf = (buf == NBUF - 1) ? 0 : buf + 1;
        }
    }
    // Drain all bulk stores before exit
    if (leader)
        asm volatile("cp.async.bulk.wait_group 0;" ::: "memory");
}

extern "C" void kernel_launch(void* const* d_in, const int* in_sizes, int n_in,
                              void* d_out, int out_size)
{
    const float* fa = (const float*)d_in[0];
    const float* ph = (const float*)d_in[1];
    const float* T1 = (const float*)d_in[2];
    const float* T2 = (const float*)d_in[3];
    const float* B0 = (const float*)d_in[4];
    const float* B1 = (const float*)d_in[5];
    const int*   tr = (const int*)d_in[6];

    int n_pulses = in_sizes[0];
    int n_batch  = in_sizes[2];
    if (n_pulses > NP) n_pulses = NP;

    int blocks = (n_batch + BPB - 1) / BPB;   // 2048
    epg_kernel<<<blocks, THREADS>>>(fa, ph, T1, T2, B0, B1, tr,
                                    (float*)d_out, n_pulses, n_batch);
}